// round 14
// baseline (speedup 1.0000x reference)
#include <cuda_runtime.h>
#include <cuda_bf16.h>
#include <stdint.h>

#define N_NODES  100000
#define N_EDGES  3200000
#define N_FEAT   128
#define HIDDEN   64
#define N_GRAPHS 256

// Padded CSC capacity: E + 3 per node + 8 slack for unroll-8 overread
#define CSC_CAP  (N_EDGES + 4 * N_NODES + 8)
#define NTB      ((N_NODES + 127) / 128)    // 782 mma row-tiles

// ---------------- device scratch ----------------
__device__ __align__(16) static __nv_bfloat162 g_P [N_NODES * 32];  // layer-1 messages
__device__ __align__(16) static __nv_bfloat162 g_P2[N_NODES * 32];  // layer-2 messages
__device__ __align__(16) static __nv_bfloat162 g_H1[N_NODES * 32];  // layer-1 out
__device__ __align__(16) static float g_pool[N_GRAPHS * 64];        // pooled sums (zeroed by k_head)
__device__ __align__(16) static int   g_csc[CSC_CAP];               // pad slots stay 0
__device__              static int   g_deg[N_NODES];                // zeroed by k_head each call
__device__              static int   g_rowptr[N_NODES];
__device__              static int   g_cursor[N_NODES];
__device__              static float g_dinv[N_NODES];
__device__              static int   g_bsum[128];

// ---------------- degree histogram, 4 edges/thread ----------------
// g_deg==0 at entry: zero-init at load; k_head restores it at the end of every call.
__global__ void k_count(const int4* __restrict__ dst4) {
    int i = blockIdx.x * blockDim.x + threadIdx.x;
    if (i < N_EDGES / 4) {
        int4 d = dst4[i];
        atomicAdd(&g_deg[d.x], 1);
        atomicAdd(&g_deg[d.y], 1);
        atomicAdd(&g_deg[d.z], 1);
        atomicAdd(&g_deg[d.w], 1);
    }
}

// ---------------- exclusive scan of padded degrees (+ dinv fused) ----------------
#define SCAN_B 1024
#define SCAN_NB ((N_NODES + SCAN_B - 1) / SCAN_B)   // 98

__global__ void k_scanA() {
    __shared__ int sm[SCAN_B];
    int i = blockIdx.x * SCAN_B + threadIdx.x;
    int v = 0;
    if (i < N_NODES) {
        int d = g_deg[i];
        g_dinv[i] = rsqrtf((float)(d + 1));          // fused dinv (self-loop +1)
        v = (d + 3) & ~3;                            // pad segment to multiple of 4
    }
    sm[threadIdx.x] = v;
    __syncthreads();
    #pragma unroll
    for (int off = 1; off < SCAN_B; off <<= 1) {
        int t = (threadIdx.x >= off) ? sm[threadIdx.x - off] : 0;
        __syncthreads();
        sm[threadIdx.x] += t;
        __syncthreads();
    }
    int inc = sm[threadIdx.x];
    if (i < N_NODES) g_rowptr[i] = inc - v;
    if (threadIdx.x == SCAN_B - 1) g_bsum[blockIdx.x] = inc;
}

// scanC with scanB merged: each block computes its own bsum-prefix directly.
__global__ void k_scanC() {
    __shared__ int soff;
    int c = blockIdx.x;
    if (threadIdx.x < 32) {
        int s = 0;
        for (int j = threadIdx.x; j < c; j += 32) s += g_bsum[j];
        #pragma unroll
        for (int o = 16; o; o >>= 1) s += __shfl_down_sync(0xFFFFFFFFu, s, o);
        if (threadIdx.x == 0) soff = s;
    }
    __syncthreads();
    int i = c * SCAN_B + threadIdx.x;
    if (i < N_NODES) {
        int r = g_rowptr[i] + soff;
        g_rowptr[i] = r;
        g_cursor[i] = r;
    }
}

// ---------------- tensor-core GEMM body: P = (A @ W) * dinv, bf16 out -------------
// mma.sync.aligned.m16n8k16.row.col.f32.bf16.bf16.f32
// Warp tile: 16 rows x 64 cols. A fragments straight from global.
// B staged in smem transposed [n][k], stride K+8 elems => conflict-free.

__device__ __forceinline__ unsigned cvt_pack_bf2(float hi, float lo) {
    unsigned r;
    asm("cvt.rn.bf16x2.f32 %0, %1, %2;" : "=r"(r) : "f"(hi), "f"(lo));
    return r;
}

__device__ __forceinline__ void mma16816(float* d, unsigned a0, unsigned a1,
                                         unsigned a2, unsigned a3,
                                         unsigned b0, unsigned b1) {
    asm("mma.sync.aligned.m16n8k16.row.col.f32.bf16.bf16.f32 "
        "{%0,%1,%2,%3}, {%4,%5,%6,%7}, {%8,%9}, {%0,%1,%2,%3};"
        : "+f"(d[0]), "+f"(d[1]), "+f"(d[2]), "+f"(d[3])
        : "r"(a0), "r"(a1), "r"(a2), "r"(a3), "r"(b0), "r"(b1));
}

template <int K, bool A_FP32>
__device__ __forceinline__ void mma_body(const void* __restrict__ Asrc,
                                         const float* __restrict__ W,
                                         __nv_bfloat162* __restrict__ Pout,
                                         __nv_bfloat16* sB,
                                         int tile0, int tstride) {
    constexpr int BSTRIDE = K + 8;                      // conflict-free LDS pattern

    for (int idx = threadIdx.x; idx < K * 64; idx += blockDim.x) {
        int k = idx >> 6, n = idx & 63;                 // W row-major [K][64]
        sB[n * BSTRIDE + k] = __float2bfloat16(W[idx]);
    }
    __syncthreads();

    int warp = threadIdx.x >> 5, lane = threadIdx.x & 31;
    int l4 = lane >> 2, lm = lane & 3;

    for (int tb = tile0; tb < NTB; tb += tstride) {
        int row0 = tb * 128 + warp * 16;
        int ra = row0 + l4;                             // rows for d0/d1
        int rb = ra + 8;                                // rows for d2/d3
        int ca = ra < N_NODES ? ra : N_NODES - 1;       // clamped load rows
        int cb = rb < N_NODES ? rb : N_NODES - 1;

        float acc[32];
        #pragma unroll
        for (int i = 0; i < 32; i++) acc[i] = 0.f;

        #pragma unroll
        for (int ks = 0; ks < K / 16; ks++) {
            int k0 = ks * 16 + lm * 2;
            unsigned a0, a1, a2, a3;
            if (A_FP32) {
                const float* X = (const float*)Asrc;
                float2 fa = *(const float2*)(X + (size_t)ca * K + k0);
                float2 fb = *(const float2*)(X + (size_t)cb * K + k0);
                float2 fc = *(const float2*)(X + (size_t)ca * K + k0 + 8);
                float2 fd = *(const float2*)(X + (size_t)cb * K + k0 + 8);
                a0 = cvt_pack_bf2(fa.y, fa.x);          // hi = k0+1, lo = k0
                a1 = cvt_pack_bf2(fb.y, fb.x);
                a2 = cvt_pack_bf2(fc.y, fc.x);
                a3 = cvt_pack_bf2(fd.y, fd.x);
            } else {
                const __nv_bfloat16* H = (const __nv_bfloat16*)Asrc;
                a0 = *(const unsigned*)(H + (size_t)ca * K + k0);
                a1 = *(const unsigned*)(H + (size_t)cb * K + k0);
                a2 = *(const unsigned*)(H + (size_t)ca * K + k0 + 8);
                a3 = *(const unsigned*)(H + (size_t)cb * K + k0 + 8);
            }
            #pragma unroll
            for (int nt = 0; nt < 8; nt++) {
                const __nv_bfloat16* bp = sB + (nt * 8 + l4) * BSTRIDE + k0;
                unsigned b0 = *(const unsigned*)bp;       // (k0,n),(k0+1,n)
                unsigned b1 = *(const unsigned*)(bp + 8); // (k0+8,n),(k0+9,n)
                mma16816(&acc[nt * 4], a0, a1, a2, a3, b0, b1);
            }
        }

        float da = g_dinv[ca], db = g_dinv[cb];
        #pragma unroll
        for (int nt = 0; nt < 8; nt++) {
            int cp = nt * 4 + lm;                       // col-pair index (c0/2)
            if (ra < N_NODES)
                Pout[ra * 32 + cp] = __floats2bfloat162_rn(acc[nt*4+0]*da, acc[nt*4+1]*da);
            if (rb < N_NODES)
                Pout[rb * 32 + cp] = __floats2bfloat162_rn(acc[nt*4+2]*db, acc[nt*4+3]*db);
        }
    }
}

// ---------------- merged: CSC fill || layer-1 GEMM (role split, no barrier) -------
// After scanC both are runnable: fill needs g_cursor, mma1 needs g_dinv only.
// Role = bid % 5: 4 fill slots : 1 mma slot (work ratio 3125 : 782).
__global__ void k_fill_mma1(const int4* __restrict__ src4, const int4* __restrict__ dst4,
                            const float* __restrict__ X, const float* __restrict__ W1,
                            __nv_bfloat162* __restrict__ Pout) {
    __shared__ __nv_bfloat16 sB[64 * (N_FEAT + 8)];     // 17.4KB (mma role only)
    int grp = blockIdx.x / 5;
    int r   = blockIdx.x % 5;
    if (r < 4) {
        int i = (grp * 4 + r) * 256 + threadIdx.x;
        if (i < N_EDGES / 4) {
            int4 s = src4[i];
            int4 d = dst4[i];
            g_csc[atomicAdd(&g_cursor[d.x], 1)] = s.x;
            g_csc[atomicAdd(&g_cursor[d.y], 1)] = s.y;
            g_csc[atomicAdd(&g_cursor[d.z], 1)] = s.z;
            g_csc[atomicAdd(&g_cursor[d.w], 1)] = s.w;
        }
    } else {
        mma_body<N_FEAT, true>((const void*)X, W1, Pout, sB, grp, NTB);
    }
}

// ---------------- standalone tensor-core GEMM (layer 2) ----------------
template <int K, bool A_FP32>
__global__ void k_mma(const void* __restrict__ Asrc, const float* __restrict__ W,
                      __nv_bfloat162* __restrict__ Pout) {
    __shared__ __nv_bfloat16 sB[64 * (K + 8)];
    mma_body<K, A_FP32>(Asrc, W, Pout, sB, blockIdx.x, gridDim.x);
}

// ---------------- gather core (bf16 messages, fp32 accumulate) ----------------
__device__ __forceinline__ float2 gather_node(const __nv_bfloat162* __restrict__ P,
                                              int n, int lane) {
    int start = g_rowptr[n];
    int end = start + g_deg[n];
    float2 acc = __bfloat1622float2(P[n * 32 + lane]);   // self term
    for (int p = start; p < end; p += 8) {
        int4 sa = *reinterpret_cast<const int4*>(g_csc + p);
        int4 sb = *reinterpret_cast<const int4*>(g_csc + p + 4);
        float2 v0 = __bfloat1622float2(P[(size_t)sa.x * 32 + lane]);
        float2 v1 = __bfloat1622float2(P[(size_t)sa.y * 32 + lane]);
        float2 v2 = __bfloat1622float2(P[(size_t)sa.z * 32 + lane]);
        float2 v3 = __bfloat1622float2(P[(size_t)sa.w * 32 + lane]);
        float2 v4 = __bfloat1622float2(P[(size_t)sb.x * 32 + lane]);
        float2 v5 = __bfloat1622float2(P[(size_t)sb.y * 32 + lane]);
        float2 v6 = __bfloat1622float2(P[(size_t)sb.z * 32 + lane]);
        float2 v7 = __bfloat1622float2(P[(size_t)sb.w * 32 + lane]);
        int rem = end - p;
        acc.x += v0.x; acc.y += v0.y;
        if (rem > 1) { acc.x += v1.x; acc.y += v1.y; }
        if (rem > 2) { acc.x += v2.x; acc.y += v2.y; }
        if (rem > 3) { acc.x += v3.x; acc.y += v3.y; }
        if (rem > 4) { acc.x += v4.x; acc.y += v4.y; }
        if (rem > 5) { acc.x += v5.x; acc.y += v5.y; }
        if (rem > 6) { acc.x += v6.x; acc.y += v6.y; }
        if (rem > 7) { acc.x += v7.x; acc.y += v7.y; }
    }
    return acc;
}

// ---------------- gather layer 1 (relu, bf16 out to H1) ----------------
__global__ void k_gather1(const float* __restrict__ bias) {
    int widx = (blockIdx.x * blockDim.x + threadIdx.x) >> 5;
    if (widx >= N_NODES) return;
    int lane = threadIdx.x & 31;
    float2 b = reinterpret_cast<const float2*>(bias)[lane];
    float dn = g_dinv[widx];
    float2 acc = gather_node(g_P, widx, lane);
    float ox = fmaxf(dn * acc.x + b.x, 0.f);
    float oy = fmaxf(dn * acc.y + b.y, 0.f);
    g_H1[widx * 32 + lane] = __floats2bfloat162_rn(ox, oy);
}

// ---------------- gather layer 2 + pooled-sum accumulation (atomics) --------------
// Keeps full per-node-warp TLP (100k warps); pool write = 2 REDs/lane into
// g_pool[graph*64 + c] (16k addresses, ~390 adds each over the kernel window).
__global__ void k_gather2(const int* __restrict__ batch,
                          const float* __restrict__ bias) {
    int widx = (blockIdx.x * blockDim.x + threadIdx.x) >> 5;
    if (widx >= N_NODES) return;
    int lane = threadIdx.x & 31;
    float2 b = reinterpret_cast<const float2*>(bias)[lane];
    float dn = g_dinv[widx];
    float2 acc = gather_node(g_P2, widx, lane);
    float ox = dn * acc.x + b.x;
    float oy = dn * acc.y + b.y;
    int g = batch[widx];
    atomicAdd(&g_pool[g * 64 + 2 * lane],     ox);
    atomicAdd(&g_pool[g * 64 + 2 * lane + 1], oy);
}

// ---------------- head: out[g] = dot(pool[g],Wl)/cnt[g] + bl ; cleanup ------------
__device__ __forceinline__ int lbound(const int* __restrict__ a, int n, int key) {
    int lo = 0, hi = n;
    while (lo < hi) {
        int m = (lo + hi) >> 1;
        if (a[m] < key) lo = m + 1; else hi = m;
    }
    return lo;
}

__global__ void k_head(const int* __restrict__ batch, const float* __restrict__ Wl,
                       const float* __restrict__ bl, float* __restrict__ out) {
    __shared__ float sw[2];
    int g = blockIdx.x;       // 256 blocks
    int t = threadIdx.x;      // 64 threads
    int lane = t & 31;
    float v = g_pool[g * 64 + t] * Wl[t];
    #pragma unroll
    for (int o = 16; o; o >>= 1) v += __shfl_down_sync(0xFFFFFFFFu, v, o);
    if (lane == 0) sw[t >> 5] = v;
    __syncthreads();
    if (t == 0) {
        int lo = lbound(batch, N_NODES, g);
        int hi = lbound(batch, N_NODES, g + 1);
        int cnt = hi - lo; if (cnt < 1) cnt = 1;
        out[g] = (sw[0] + sw[1]) / (float)cnt + bl[0];
    }
    // cleanup for next call (stream-serialized; zero-init covers the first call)
    g_pool[g * 64 + t] = 0.f;
    for (int i = g * 64 + t; i < N_NODES; i += N_GRAPHS * 64) g_deg[i] = 0;
}

// ---------------- launch: 8 kernels, single stream ----------------
extern "C" void kernel_launch(void* const* d_in, const int* in_sizes, int n_in,
                              void* d_out, int out_size) {
    const float* x     = (const float*)d_in[0];
    const int*   eidx  = (const int*)d_in[1];
    const int*   batch = (const int*)d_in[2];
    const float* W1    = (const float*)d_in[3];
    const float* b1    = (const float*)d_in[4];
    const float* W2    = (const float*)d_in[5];
    const float* b2    = (const float*)d_in[6];
    const float* Wl    = (const float*)d_in[7];
    const float* bl    = (const float*)d_in[8];
    float* out = (float*)d_out;

    const int4* src4 = (const int4*)eidx;
    const int4* dst4 = (const int4*)(eidx + N_EDGES);

    __nv_bfloat162* H1v; cudaGetSymbolAddress((void**)&H1v, g_H1);
    __nv_bfloat162* Pv;  cudaGetSymbolAddress((void**)&Pv,  g_P);
    __nv_bfloat162* P2v; cudaGetSymbolAddress((void**)&P2v, g_P2);

    int nThreads = 256;
    int nbEdge4 = (N_EDGES / 4 + nThreads - 1) / nThreads;

    // --- CSC build prefix (deg/scan); g_deg pre-zeroed by previous call's k_head ---
    k_count<<<nbEdge4, nThreads>>>(dst4);
    k_scanA<<<SCAN_NB, SCAN_B>>>();
    k_scanC<<<SCAN_NB, SCAN_B>>>();

    // --- CSC fill || layer-1 GEMM (role-split, no dependency between them) ---
    k_fill_mma1<<<NTB * 5, 256>>>(src4, dst4, x, W1, Pv);

    // --- layer 1 gather ---
    k_gather1<<<(N_NODES * 32 + 255) / 256, 256>>>(b1);

    // --- layer 2: tensor-core GEMM (H1 bf16 direct) + gather w/ pooled atomics ---
    k_mma<HIDDEN, false><<<NTB, 256>>>((const void*)H1v, W2, P2v);
    k_gather2<<<(N_NODES * 32 + 255) / 256, 256>>>(batch, b2);

    // --- head (+ cleanup of g_pool / g_deg for the next call) ---
    k_head<<<N_GRAPHS, 64>>>(batch, Wl, bl, out);
}